// round 1
// baseline (speedup 1.0000x reference)
#include <cuda_runtime.h>
#include <math.h>

#define BS     4096
#define HID    128
#define NREL   1000
#define NIDX   (8192*3)
#define TILE   64
#define KC     16

// ---------------- device scratch (no allocations allowed) ----------------
__device__ double g_h2, g_r2, g_t2, g_wr, g_margin;
__device__ int    g_win[NREL];
__device__ int    g_mode;                 // 1 = input was int64, 0 = int32
__device__ int    g_idx[NIDX];
__device__ float  g_err[8192 * HID];      // rows 0..4095 = ep, 4096..8191 = en
__device__ float  g_A[BS], g_B[BS], g_C[BS];

// ---------------- init: zero accumulators, reset winners ----------------
__global__ void k_init() {
    int t = blockIdx.x * blockDim.x + threadIdx.x;
    if (t == 0) { g_h2 = 0.0; g_r2 = 0.0; g_t2 = 0.0; g_wr = 0.0; g_margin = 0.0; }
    if (t < NREL) g_win[t] = -1;
}

// ---------------- detect int32 vs int64 index encoding ----------------
// If input is int64 (little-endian), every odd 32-bit word within the first
// 24576 words is a high half == 0 (values are in [0,1000)). If int32, odd
// words are real indices and are essentially never ALL zero.
__global__ void k_detect(const int* __restrict__ in32) {
    __shared__ int s_nz;
    if (threadIdx.x == 0) s_nz = 0;
    __syncthreads();
    int nz = 0;
    for (int i = threadIdx.x; i < NIDX / 2; i += blockDim.x)
        if (in32[2 * i + 1] != 0) nz = 1;
    if (nz) s_nz = 1;
    __syncthreads();
    if (threadIdx.x == 0) g_mode = s_nz ? 0 : 1;
}

__global__ void k_convert(const int* __restrict__ in32) {
    int i = blockIdx.x * blockDim.x + threadIdx.x;
    if (i < NIDX) g_idx[i] = g_mode ? in32[2 * i] : in32[i];
}

// ---------------- gather + error + per-row dots + norms + winner ----------------
__global__ void k_gather(const float* __restrict__ ent, const float* __restrict__ rel) {
    int j = blockIdx.x;          // 0..4095
    int d = threadIdx.x;         // 0..127
    int hp = g_idx[j * 3 + 0], rp = g_idx[j * 3 + 1], tp = g_idx[j * 3 + 2];
    int jn = j + BS;
    int hn = g_idx[jn * 3 + 0], rn = g_idx[jn * 3 + 1], tn = g_idx[jn * 3 + 2];

    float hv0 = ent[hp * HID + d], rv0 = rel[rp * HID + d], tv0 = ent[tp * HID + d];
    float hv1 = ent[hn * HID + d], rv1 = rel[rn * HID + d], tv1 = ent[tn * HID + d];
    float ep = fabsf(hv0 + rv0 - tv0);
    float en = fabsf(hv1 + rv1 - tv1);
    g_err[j * HID + d]  = ep;
    g_err[jn * HID + d] = en;

    __shared__ float red[6][HID];
    red[0][d] = hv0 * hv0 + hv1 * hv1;
    red[1][d] = rv0 * rv0 + rv1 * rv1;
    red[2][d] = tv0 * tv0 + tv1 * tv1;
    red[3][d] = ep * en;
    red[4][d] = ep * ep;
    red[5][d] = en * en;
    __syncthreads();
    for (int s = HID / 2; s > 0; s >>= 1) {
        if (d < s) {
            #pragma unroll
            for (int q = 0; q < 6; q++) red[q][d] += red[q][d + s];
        }
        __syncthreads();
    }
    if (d == 0) {
        atomicAdd(&g_h2, (double)red[0][0]);
        atomicAdd(&g_r2, (double)red[1][0]);
        atomicAdd(&g_t2, (double)red[2][0]);
        float a = red[3][0], b = red[4][0], c = red[5][0];
        g_A[j] = a; g_B[j] = b; g_C[j] = c;
        // ||en⊗en - ep⊗ep||_F^2 = b^2 + c^2 - 2 a^2
        atomicAdd(&g_wr, (double)b * b + (double)c * c - 2.0 * (double)a * a);
        atomicMax(&g_win[rp], j);   // last occurrence wins
    }
}

// ---------------- write Wr_new ----------------
__global__ void k_wr(const float* __restrict__ Wr, float* __restrict__ outWr) {
    int r = blockIdx.x;
    int w = g_win[r];
    __shared__ float sp[HID], sn[HID];
    if (w >= 0) {
        if (threadIdx.x < HID) {
            sp[threadIdx.x] = g_err[w * HID + threadIdx.x];
            sn[threadIdx.x] = g_err[(w + BS) * HID + threadIdx.x];
        }
        __syncthreads();
        for (int e = threadIdx.x; e < HID * HID; e += blockDim.x) {
            int hh = e >> 7, kk = e & (HID - 1);
            outWr[(size_t)r * HID * HID + e] = sn[hh] * sn[kk] - sp[hh] * sp[kk];
        }
    } else {
        for (int e = threadIdx.x; e < HID * HID; e += blockDim.x)
            outWr[(size_t)r * HID * HID + e] = Wr[(size_t)r * HID * HID + e];
    }
}

// ---------------- fused 4-product GEMM + relu-sum ----------------
// score(i,j) = a_j*(ep_i.en_j + en_i.ep_j) - b_j*(ep_i.ep_j) - c_j*(en_i.en_j)
__global__ __launch_bounds__(256) void k_score() {
    int I0 = blockIdx.y * TILE;
    int J0 = blockIdx.x * TILE;
    int tx = threadIdx.x & 15, ty = threadIdx.x >> 4;

    __shared__ float sPI[TILE][KC + 1];
    __shared__ float sNI[TILE][KC + 1];
    __shared__ float sPJ[TILE][KC + 1];
    __shared__ float sNJ[TILE][KC + 1];

    float g1[4][4] = {}, g2[4][4] = {}, g3[4][4] = {}, g4[4][4] = {};

    const float* epb = g_err;
    const float* enb = g_err + (size_t)BS * HID;

    int lrow = threadIdx.x >> 2;          // 0..63
    int lseg = (threadIdx.x & 3) * 4;     // 0,4,8,12

    for (int kc = 0; kc < HID; kc += KC) {
        __syncthreads();
        float4 v;
        v = *(const float4*)&epb[(size_t)(I0 + lrow) * HID + kc + lseg];
        sPI[lrow][lseg + 0] = v.x; sPI[lrow][lseg + 1] = v.y; sPI[lrow][lseg + 2] = v.z; sPI[lrow][lseg + 3] = v.w;
        v = *(const float4*)&enb[(size_t)(I0 + lrow) * HID + kc + lseg];
        sNI[lrow][lseg + 0] = v.x; sNI[lrow][lseg + 1] = v.y; sNI[lrow][lseg + 2] = v.z; sNI[lrow][lseg + 3] = v.w;
        v = *(const float4*)&epb[(size_t)(J0 + lrow) * HID + kc + lseg];
        sPJ[lrow][lseg + 0] = v.x; sPJ[lrow][lseg + 1] = v.y; sPJ[lrow][lseg + 2] = v.z; sPJ[lrow][lseg + 3] = v.w;
        v = *(const float4*)&enb[(size_t)(J0 + lrow) * HID + kc + lseg];
        sNJ[lrow][lseg + 0] = v.x; sNJ[lrow][lseg + 1] = v.y; sNJ[lrow][lseg + 2] = v.z; sNJ[lrow][lseg + 3] = v.w;
        __syncthreads();

        #pragma unroll
        for (int k = 0; k < KC; k++) {
            float pI[4], nI[4], pJ[4], nJ[4];
            #pragma unroll
            for (int r = 0; r < 4; r++) {
                pI[r] = sPI[ty * 4 + r][k];
                nI[r] = sNI[ty * 4 + r][k];
                pJ[r] = sPJ[tx * 4 + r][k];
                nJ[r] = sNJ[tx * 4 + r][k];
            }
            #pragma unroll
            for (int i = 0; i < 4; i++) {
                #pragma unroll
                for (int j2 = 0; j2 < 4; j2++) {
                    g1[i][j2] = fmaf(pI[i], nJ[j2], g1[i][j2]);
                    g2[i][j2] = fmaf(pI[i], pJ[j2], g2[i][j2]);
                    g3[i][j2] = fmaf(nI[i], nJ[j2], g3[i][j2]);
                    g4[i][j2] = fmaf(nI[i], pJ[j2], g4[i][j2]);
                }
            }
        }
    }

    float aj[4], bj[4], cj[4];
    #pragma unroll
    for (int j2 = 0; j2 < 4; j2++) {
        int jg = J0 + tx * 4 + j2;
        aj[j2] = g_A[jg]; bj[j2] = g_B[jg]; cj[j2] = g_C[jg];
    }
    float sum = 0.0f;
    #pragma unroll
    for (int i = 0; i < 4; i++) {
        #pragma unroll
        for (int j2 = 0; j2 < 4; j2++) {
            float x = aj[j2] * (g1[i][j2] + g4[i][j2]) - bj[j2] * g2[i][j2] - cj[j2] * g3[i][j2] + 1.0f;
            sum += fmaxf(x, 0.0f);
        }
    }

    __shared__ float red[256];
    red[threadIdx.x] = sum;
    __syncthreads();
    for (int s = 128; s > 0; s >>= 1) {
        if (threadIdx.x < s) red[threadIdx.x] += red[threadIdx.x + s];
        __syncthreads();
    }
    if (threadIdx.x == 0) atomicAdd(&g_margin, (double)red[0]);
}

// ---------------- finalize ----------------
__global__ void k_final(float* __restrict__ out) {
    double margin = g_margin / (double)BS;
    double wr = sqrt(g_wr) * 0.01;
    double nl = (sqrt(g_h2) + sqrt(g_r2) + sqrt(g_t2)) * 0.01;
    out[0] = (float)(margin + wr + nl);
}

// ---------------- launch ----------------
extern "C" void kernel_launch(void* const* d_in, const int* in_sizes, int n_in,
                              void* d_out, int out_size) {
    const int*   in32 = (const int*)d_in[0];
    const float* ent  = (const float*)d_in[1];
    const float* rel  = (const float*)d_in[2];
    const float* Wr   = (const float*)d_in[3];
    float* out = (float*)d_out;

    k_init<<<4, 256>>>();
    k_detect<<<1, 256>>>(in32);
    k_convert<<<(NIDX + 255) / 256, 256>>>(in32);
    k_gather<<<BS, HID>>>(ent, rel);
    k_wr<<<NREL, 256>>>(Wr, out + 1);
    k_score<<<dim3(BS / TILE, BS / TILE), 256>>>();
    k_final<<<1, 1>>>(out);
}

// round 9
// speedup vs baseline: 4.5345x; 4.5345x over previous
#include <cuda_runtime.h>
#include <math.h>

#define BS     4096
#define HID    128
#define NREL   1000
#define NIDX   (8192*3)

// ---------------- device scratch (no allocations allowed) ----------------
__device__ double g_h2, g_r2, g_t2, g_wr, g_margin;
__device__ int    g_win[NREL];
__device__ int    g_mode;                 // 1 = input was int64, 0 = int32
__device__ int    g_idx[NIDX];
__device__ float  g_err[8192 * HID];      // exact fp32: rows 0..4095 = ep, 4096..8191 = en
__device__ float  g_U[BS * 256];          // tf32-rounded [ep_i | en_i]
__device__ float  g_W[BS * 256];          // tf32-rounded [a*en-b*ep | a*ep-c*en]

__device__ __forceinline__ float tf32r(float x) {
    unsigned u; asm("cvt.rna.tf32.f32 %0, %1;" : "=r"(u) : "f"(x));
    return __uint_as_float(u);
}

// ---------------- init ----------------
__global__ void k_init() {
    int t = blockIdx.x * blockDim.x + threadIdx.x;
    if (t == 0) { g_h2 = 0.0; g_r2 = 0.0; g_t2 = 0.0; g_wr = 0.0; g_margin = 0.0; }
    if (t < NREL) g_win[t] = -1;
}

// ---------------- int32 vs int64 detection ----------------
__global__ void k_detect(const int* __restrict__ in32) {
    __shared__ int s_nz;
    if (threadIdx.x == 0) s_nz = 0;
    __syncthreads();
    int nz = 0;
    for (int i = threadIdx.x; i < NIDX / 2; i += blockDim.x)
        if (in32[2 * i + 1] != 0) nz = 1;
    if (nz) s_nz = 1;
    __syncthreads();
    if (threadIdx.x == 0) g_mode = s_nz ? 0 : 1;
}

__global__ void k_convert(const int* __restrict__ in32) {
    int i = blockIdx.x * blockDim.x + threadIdx.x;
    if (i < NIDX) g_idx[i] = g_mode ? in32[2 * i] : in32[i];
}

// ---------------- gather + per-row dots + norms + winner + U/W build ----------------
__global__ void k_gather(const float* __restrict__ ent, const float* __restrict__ rel) {
    int j = blockIdx.x;          // 0..4095
    int d = threadIdx.x;         // 0..127
    int hp = g_idx[j * 3 + 0], rp = g_idx[j * 3 + 1], tp = g_idx[j * 3 + 2];
    int jn = j + BS;
    int hn = g_idx[jn * 3 + 0], rn = g_idx[jn * 3 + 1], tn = g_idx[jn * 3 + 2];

    float hv0 = ent[hp * HID + d], rv0 = rel[rp * HID + d], tv0 = ent[tp * HID + d];
    float hv1 = ent[hn * HID + d], rv1 = rel[rn * HID + d], tv1 = ent[tn * HID + d];
    float ep = fabsf(hv0 + rv0 - tv0);
    float en = fabsf(hv1 + rv1 - tv1);
    g_err[j * HID + d]  = ep;
    g_err[jn * HID + d] = en;

    __shared__ float red[6][HID];
    red[0][d] = hv0 * hv0 + hv1 * hv1;
    red[1][d] = rv0 * rv0 + rv1 * rv1;
    red[2][d] = tv0 * tv0 + tv1 * tv1;
    red[3][d] = ep * en;
    red[4][d] = ep * ep;
    red[5][d] = en * en;
    __syncthreads();
    for (int s = HID / 2; s > 0; s >>= 1) {
        if (d < s) {
            #pragma unroll
            for (int q = 0; q < 6; q++) red[q][d] += red[q][d + s];
        }
        __syncthreads();
    }
    float a = red[3][0], b = red[4][0], c = red[5][0];

    // tf32-rounded operands for the score GEMM (K=256 fused formulation)
    g_U[(size_t)j * 256 + d]       = tf32r(ep);
    g_U[(size_t)j * 256 + 128 + d] = tf32r(en);
    g_W[(size_t)j * 256 + d]       = tf32r(a * en - b * ep);   //  vp
    g_W[(size_t)j * 256 + 128 + d] = tf32r(a * ep - c * en);   // -vn

    if (d == 0) {
        atomicAdd(&g_h2, (double)red[0][0]);
        atomicAdd(&g_r2, (double)red[1][0]);
        atomicAdd(&g_t2, (double)red[2][0]);
        atomicAdd(&g_wr, (double)b * b + (double)c * c - 2.0 * (double)a * a);
        atomicMax(&g_win[rp], j);   // last occurrence wins
    }
}

// ---------------- write Wr_new (exact fp32) ----------------
// NOTE: outWr = out + 1 is only 4-byte aligned -> scalar stores ONLY.
__global__ void k_wr(const float* __restrict__ Wr, float* __restrict__ outWr) {
    int r = blockIdx.x;
    int w = g_win[r];
    __shared__ float sp[HID], sn[HID];
    if (w >= 0) {
        if (threadIdx.x < HID) {
            sp[threadIdx.x] = g_err[w * HID + threadIdx.x];
            sn[threadIdx.x] = g_err[(w + BS) * HID + threadIdx.x];
        }
        __syncthreads();
        for (int e4 = threadIdx.x; e4 < HID * HID / 4; e4 += blockDim.x) {
            int e = e4 * 4;
            int hh = e >> 7, kk = e & (HID - 1);
            float snh = sn[hh], sph = sp[hh];
            size_t base = (size_t)r * HID * HID + e;
            outWr[base + 0] = snh * sn[kk + 0] - sph * sp[kk + 0];
            outWr[base + 1] = snh * sn[kk + 1] - sph * sp[kk + 1];
            outWr[base + 2] = snh * sn[kk + 2] - sph * sp[kk + 2];
            outWr[base + 3] = snh * sn[kk + 3] - sph * sp[kk + 3];
        }
    } else {
        for (int e4 = threadIdx.x; e4 < HID * HID / 4; e4 += blockDim.x) {
            // float4 load from aligned input Wr, scalar stores to unaligned outWr
            float4 v = *(const float4*)&Wr[(size_t)r * HID * HID + e4 * 4];
            size_t base = (size_t)r * HID * HID + e4 * 4;
            outWr[base + 0] = v.x;
            outWr[base + 1] = v.y;
            outWr[base + 2] = v.z;
            outWr[base + 3] = v.w;
        }
    }
}

// ---------------- tf32 tensor-core score GEMM + relu-sum ----------------
// score = U @ W^T (4096x4096, K=256); margin += sum(relu(score + 1))
__device__ __forceinline__ void mma_tf32(float* d, const unsigned* a, const unsigned* b) {
    asm volatile(
        "mma.sync.aligned.m16n8k8.row.col.f32.tf32.tf32.f32 "
        "{%0,%1,%2,%3}, {%4,%5,%6,%7}, {%8,%9}, {%0,%1,%2,%3};\n"
        : "+f"(d[0]), "+f"(d[1]), "+f"(d[2]), "+f"(d[3])
        : "r"(a[0]), "r"(a[1]), "r"(a[2]), "r"(a[3]), "r"(b[0]), "r"(b[1]));
}

__global__ __launch_bounds__(256) void k_score_mma() {
    // block tile 128(M) x 128(N); 8 warps as 2(M) x 4(N); warp tile 64x32
    __shared__ float sA[128][36];
    __shared__ float sB[128][36];
    int I0 = blockIdx.y * 128, J0 = blockIdx.x * 128;
    int tid = threadIdx.x;
    int warp = tid >> 5, lane = tid & 31;
    int wm = warp & 1, wn = warp >> 1;

    float acc[4][4][4] = {};   // [mi][ni][reg]

    for (int kt = 0; kt < 256; kt += 32) {
        __syncthreads();
        #pragma unroll
        for (int q = 0; q < 4; q++) {
            int idx = q * 256 + tid;        // float4 index, 1024 total
            int r = idx >> 3;               // 8 float4 per 32-col row
            int c = (idx & 7) * 4;
            float4 v = *(const float4*)&g_U[(size_t)(I0 + r) * 256 + kt + c];
            sA[r][c] = v.x; sA[r][c + 1] = v.y; sA[r][c + 2] = v.z; sA[r][c + 3] = v.w;
            float4 w = *(const float4*)&g_W[(size_t)(J0 + r) * 256 + kt + c];
            sB[r][c] = w.x; sB[r][c + 1] = w.y; sB[r][c + 2] = w.z; sB[r][c + 3] = w.w;
        }
        __syncthreads();

        #pragma unroll
        for (int k8 = 0; k8 < 32; k8 += 8) {
            unsigned af[4][4], bf[4][2];
            #pragma unroll
            for (int mi = 0; mi < 4; mi++) {
                int r0 = wm * 64 + mi * 16 + (lane >> 2);
                int kk = k8 + (lane & 3);
                af[mi][0] = __float_as_uint(sA[r0][kk]);
                af[mi][1] = __float_as_uint(sA[r0 + 8][kk]);
                af[mi][2] = __float_as_uint(sA[r0][kk + 4]);
                af[mi][3] = __float_as_uint(sA[r0 + 8][kk + 4]);
            }
            #pragma unroll
            for (int ni = 0; ni < 4; ni++) {
                int c0 = wn * 32 + ni * 8 + (lane >> 2);
                int kk = k8 + (lane & 3);
                bf[ni][0] = __float_as_uint(sB[c0][kk]);
                bf[ni][1] = __float_as_uint(sB[c0][kk + 4]);
            }
            #pragma unroll
            for (int mi = 0; mi < 4; mi++)
                #pragma unroll
                for (int ni = 0; ni < 4; ni++)
                    mma_tf32(acc[mi][ni], af[mi], bf[ni]);
        }
    }

    float sum = 0.0f;
    #pragma unroll
    for (int mi = 0; mi < 4; mi++)
        #pragma unroll
        for (int ni = 0; ni < 4; ni++)
            #pragma unroll
            for (int q = 0; q < 4; q++)
                sum += fmaxf(acc[mi][ni][q] + 1.0f, 0.0f);

    __shared__ float red[256];
    red[tid] = sum;
    __syncthreads();
    for (int s = 128; s > 0; s >>= 1) {
        if (tid < s) red[tid] += red[tid + s];
        __syncthreads();
    }
    if (tid == 0) atomicAdd(&g_margin, (double)red[0]);
}

// ---------------- finalize ----------------
__global__ void k_final(float* __restrict__ out) {
    double margin = g_margin / (double)BS;
    double wr = sqrt(g_wr) * 0.01;
    double nl = (sqrt(g_h2) + sqrt(g_r2) + sqrt(g_t2)) * 0.01;
    out[0] = (float)(margin + wr + nl);
}

// ---------------- launch ----------------
extern "C" void kernel_launch(void* const* d_in, const int* in_sizes, int n_in,
                              void* d_out, int out_size) {
    const int*   in32 = (const int*)d_in[0];
    const float* ent  = (const float*)d_in[1];
    const float* rel  = (const float*)d_in[2];
    const float* Wr   = (const float*)d_in[3];
    float* out = (float*)d_out;

    k_init<<<4, 256>>>();
    k_detect<<<1, 256>>>(in32);
    k_convert<<<(NIDX + 255) / 256, 256>>>(in32);
    k_gather<<<BS, HID>>>(ent, rel);
    k_wr<<<NREL, 256>>>(Wr, out + 1);
    k_score_mma<<<dim3(BS / 128, BS / 128), 256>>>();
    k_final<<<1, 1>>>(out);
}